// round 7
// baseline (speedup 1.0000x reference)
#include <cuda_runtime.h>
#include <cuda_bf16.h>
#include <cstdint>

#define Bv 16
#define Nv 1024
#define Cv 768
#define Hv 12
#define HD 64
#define C3 2304
#define MT (Bv*Nv)   // 16384

// ======================= device scratch =======================
__device__ float g_sig[Bv * C3];
__device__ __nv_bfloat16 g_xhi[(size_t)MT * Cv],  g_xlo[(size_t)MT * Cv];
__device__ __nv_bfloat16 g_w1hi[(size_t)C3 * Cv], g_w1lo[(size_t)C3 * Cv];
__device__ __nv_bfloat16 g_w2hi[(size_t)Cv * Cv], g_w2lo[(size_t)Cv * Cv];
__device__ __nv_bfloat16 g_qh[(size_t)MT * Cv],   g_ql[(size_t)MT * Cv];   // (b,h,n,hd)
__device__ __nv_bfloat16 g_kh[(size_t)MT * Cv],   g_kl[(size_t)MT * Cv];
__device__ __nv_bfloat16 g_vh[(size_t)MT * Cv],   g_vl[(size_t)MT * Cv];
__device__ __nv_bfloat16 g_ohi[(size_t)MT * Cv],  g_olo[(size_t)MT * Cv];  // (b,n,c)

// ======================= PTX helpers (baseline ISA only) =======================
__device__ __forceinline__ uint32_t smem_u32(const void* p) {
    uint32_t a;
    asm("{ .reg .u64 t; cvta.to.shared.u64 t, %1; cvt.u32.u64 %0, t; }" : "=r"(a) : "l"(p));
    return a;
}
__device__ __forceinline__ void ldm_x4(uint32_t& r0, uint32_t& r1, uint32_t& r2, uint32_t& r3,
                                       uint32_t addr) {
    asm volatile("ldmatrix.sync.aligned.m8n8.x4.shared.b16 {%0,%1,%2,%3}, [%4];"
                 : "=r"(r0), "=r"(r1), "=r"(r2), "=r"(r3) : "r"(addr));
}
__device__ __forceinline__ void ldm_x4_t(uint32_t& r0, uint32_t& r1, uint32_t& r2, uint32_t& r3,
                                         uint32_t addr) {
    asm volatile("ldmatrix.sync.aligned.m8n8.x4.trans.shared.b16 {%0,%1,%2,%3}, [%4];"
                 : "=r"(r0), "=r"(r1), "=r"(r2), "=r"(r3) : "r"(addr));
}
__device__ __forceinline__ void mma_bf16(float* d, const uint32_t* a, const uint32_t* b) {
    asm volatile(
        "mma.sync.aligned.m16n8k16.row.col.f32.bf16.bf16.f32 "
        "{%0,%1,%2,%3}, {%4,%5,%6,%7}, {%8,%9}, {%0,%1,%2,%3};"
        : "+f"(d[0]), "+f"(d[1]), "+f"(d[2]), "+f"(d[3])
        : "r"(a[0]), "r"(a[1]), "r"(a[2]), "r"(a[3]), "r"(b[0]), "r"(b[1]));
}
__device__ __forceinline__ void cp16(uint32_t dst, const void* src) {
    asm volatile("cp.async.cg.shared.global [%0], [%1], 16;" :: "r"(dst), "l"(src));
}
#define CP_COMMIT() asm volatile("cp.async.commit_group;" ::: "memory")
#define CP_WAIT1()  asm volatile("cp.async.wait_group 1;" ::: "memory")

__device__ __forceinline__ void split8(float4 v0, float4 v1, uint4& hi, uint4& lo) {
    float f[8] = {v0.x, v0.y, v0.z, v0.w, v1.x, v1.y, v1.z, v1.w};
    __nv_bfloat16 h[8], l[8];
    #pragma unroll
    for (int i = 0; i < 8; i++) {
        h[i] = __float2bfloat16(f[i]);
        l[i] = __float2bfloat16(f[i] - __bfloat162float(h[i]));
    }
    hi = *(uint4*)h;
    lo = *(uint4*)l;
}
__device__ __forceinline__ void split2(float x, float y, uint32_t& hi, uint32_t& lo) {
    __nv_bfloat162 h = __floats2bfloat162_rn(x, y);
    __nv_bfloat162 l = __floats2bfloat162_rn(x - __bfloat162float(h.x),
                                             y - __bfloat162float(h.y));
    hi = *(uint32_t*)&h;
    lo = *(uint32_t*)&l;
}

// ======================= gate =======================
__global__ void gate_kernel(const float* __restrict__ alpha,
                            const int* __restrict__ label) {
    int i = blockIdx.x * 256 + threadIdx.x;
    if (i >= Bv * C3) return;
    int b = i / C3;
    int d = i - b * C3;
    float a = alpha[(size_t)label[b] * C3 + d];
    g_sig[i] = 1.0f / (1.0f + __expf(-a));
}

// ======================= fp32 -> bf16 hi/lo split =======================
template<int SEL>
__global__ void split_kernel(const float* __restrict__ src, int n8) {
    int i = blockIdx.x * 256 + threadIdx.x;
    if (i >= n8) return;
    __nv_bfloat16* hi = (SEL == 0) ? g_xhi : (SEL == 1) ? g_w1hi : g_w2hi;
    __nv_bfloat16* lo = (SEL == 0) ? g_xlo : (SEL == 1) ? g_w1lo : g_w2lo;
    const float4* s = (const float4*)src + (size_t)i * 2;
    uint4 h, l;
    split8(s[0], s[1], h, l);
    *(uint4*)(hi + (size_t)i * 8) = h;
    *(uint4*)(lo + (size_t)i * 8) = l;
}

// ======================= split-bf16 HMMA GEMM, K-chunk 32, 2 CTAs/SM =======================
#define LDP 40
#define TILEB (128*LDP*2)           // one 128x32 bf16 tile (padded to 40), bytes = 10240
#define BUFB  (4*TILEB)             // AH, AL, BH, BL = 40960
#define SM_BYTES (2*BUFB)           // 81920 -> 2 CTAs/SM

// EPI 0 = qkv, EPI 1 = proj
template<int EPI>
__global__ __launch_bounds__(256, 2)
void mma_gemm(const float* __restrict__ bias, float* __restrict__ out) {
    extern __shared__ __align__(16) char sm[];
    const uint32_t sb = smem_u32(sm);

    const int tid = threadIdx.x;
    const int wid = tid >> 5;
    const int lane = tid & 31;
    const int m0 = blockIdx.y * 128;
    const int n0 = blockIdx.x * 128;
    const int wm = (wid & 1) * 64;
    const int wn = (wid >> 1) * 32;

    const __nv_bfloat16* Ah = (EPI == 0) ? g_xhi : g_ohi;
    const __nv_bfloat16* Al = (EPI == 0) ? g_xlo : g_olo;
    const __nv_bfloat16* Bh = (EPI == 0) ? g_w1hi : g_w2hi;
    const __nv_bfloat16* Bl = (EPI == 0) ? g_w1lo : g_w2lo;

    const int srow = tid >> 2;      // 0..63
    const int sg = tid & 3;

    const int grp = lane >> 3, lr = lane & 7;
    const int aRow = (grp & 1) * 8 + lr;
    const int aCol = (grp >> 1) * 8;
    const int bRow = (grp >> 1) * 8 + lr;
    const int bCol = (grp & 1) * 8;

    float acc[4][4][4] = {};

    auto issue = [&](int kc, int bsel) {
        const int k0 = kc * 32;
        const __nv_bfloat16* s0 = Ah + (size_t)m0 * Cv + k0;
        const __nv_bfloat16* s1 = Al + (size_t)m0 * Cv + k0;
        const __nv_bfloat16* s2 = Bh + (size_t)n0 * Cv + k0;
        const __nv_bfloat16* s3 = Bl + (size_t)n0 * Cv + k0;
        const uint32_t db = sb + bsel * BUFB;
        #pragma unroll
        for (int j = 0; j < 2; j++) {
            int row = srow + j * 64;
            uint32_t doff = (uint32_t)(row * LDP + sg * 8) * 2;
            size_t goff = (size_t)row * Cv + sg * 8;
            cp16(db + 0 * TILEB + doff, s0 + goff);
            cp16(db + 1 * TILEB + doff, s1 + goff);
            cp16(db + 2 * TILEB + doff, s2 + goff);
            cp16(db + 3 * TILEB + doff, s3 + goff);
        }
    };

    issue(0, 0); CP_COMMIT();
    issue(1, 1); CP_COMMIT();

    for (int kc = 0; kc < 24; kc++) {
        CP_WAIT1();
        __syncthreads();
        const uint32_t db = sb + (kc & 1) * BUFB;

        #pragma unroll
        for (int kk = 0; kk < 2; kk++) {
            // ---- B fragments once per kk (16 regs live) ----
            uint32_t bh[4][2], bl[4][2];
            #pragma unroll
            for (int np = 0; np < 2; np++) {
                uint32_t off = (uint32_t)((wn + np * 16 + bRow) * LDP + kk * 16 + bCol) * 2;
                uint32_t r0, r1, r2, r3;
                ldm_x4(r0, r1, r2, r3, db + 2 * TILEB + off);
                bh[np * 2][0] = r0; bh[np * 2][1] = r1;
                bh[np * 2 + 1][0] = r2; bh[np * 2 + 1][1] = r3;
                ldm_x4(r0, r1, r2, r3, db + 3 * TILEB + off);
                bl[np * 2][0] = r0; bl[np * 2][1] = r1;
                bl[np * 2 + 1][0] = r2; bl[np * 2 + 1][1] = r3;
            }
            // ---- A fragments per mi (8 regs, consumed immediately) ----
            #pragma unroll
            for (int mi = 0; mi < 4; mi++) {
                uint32_t ah[4], al[4];
                uint32_t off = (uint32_t)((wm + mi * 16 + aRow) * LDP + kk * 16 + aCol) * 2;
                ldm_x4(ah[0], ah[1], ah[2], ah[3], db + off);
                ldm_x4(al[0], al[1], al[2], al[3], db + TILEB + off);
                #pragma unroll
                for (int nj = 0; nj < 4; nj++) {
                    mma_bf16(acc[mi][nj], ah, bh[nj]);
                    mma_bf16(acc[mi][nj], ah, bl[nj]);
                    mma_bf16(acc[mi][nj], al, bh[nj]);
                }
            }
        }
        __syncthreads();
        if (kc + 2 < 24) issue(kc + 2, kc & 1);
        CP_COMMIT();
    }

    // ---- epilogue ----
    const int tq = n0 / Cv;
    #pragma unroll
    for (int mi = 0; mi < 4; mi++) {
        #pragma unroll
        for (int nj = 0; nj < 4; nj++) {
            int r = m0 + wm + mi * 16 + (lane >> 2);
            int c = n0 + wn + nj * 8 + 2 * (lane & 3);
            #pragma unroll
            for (int half = 0; half < 2; half++) {
                int rr = r + half * 8;
                float v0 = acc[mi][nj][half * 2 + 0];
                float v1 = acc[mi][nj][half * 2 + 1];
                float2 bi = *(const float2*)(bias + c);
                if (EPI == 0) {
                    int b = rr >> 10;
                    int n = rr & 1023;
                    float2 sg2 = *(const float2*)(g_sig + b * C3 + c);
                    float ox = (v0 + bi.x) * sg2.x;
                    float oy = (v1 + bi.y) * sg2.y;
                    int rem = c - tq * Cv;
                    int h = rem >> 6;
                    int e = rem & 63;
                    __nv_bfloat16* dh = (tq == 0) ? g_qh : (tq == 1) ? g_kh : g_vh;
                    __nv_bfloat16* dl = (tq == 0) ? g_ql : (tq == 1) ? g_kl : g_vl;
                    size_t idx = ((size_t)(b * Hv + h) * Nv + n) * HD + e;
                    uint32_t hh, ll;
                    split2(ox, oy, hh, ll);
                    *(uint32_t*)(dh + idx) = hh;
                    *(uint32_t*)(dl + idx) = ll;
                } else {
                    float2 o;
                    o.x = v0 + bi.x;
                    o.y = v1 + bi.y;
                    *(float2*)(out + (size_t)rr * Cv + c) = o;
                }
            }
        }
    }
}

// ======================= split-bf16 HMMA flash attention =======================
#define LDV 72
#define VTILEB (64*LDV*2)
#define ABUFB (4*VTILEB)
#define ASM_BYTES (2*ABUFB)         // 73728

__global__ __launch_bounds__(256, 2) void attn_mma() {
    extern __shared__ __align__(16) char sm[];
    const uint32_t sb = smem_u32(sm);

    const int tid = threadIdx.x;
    const int wid = tid >> 5;
    const int lane = tid & 31;
    const int bh = blockIdx.y;
    const size_t head_base = (size_t)bh * Nv * HD;
    const int q0 = blockIdx.x * 128 + wid * 16;

    const int grp = lane >> 3, lr = lane & 7;
    const int bRow = (grp >> 1) * 8 + lr;
    const int bCol = (grp & 1) * 8;
    const int vRow = lane & 15;
    const int vCol = (lane >> 4) * 8;

    const int srow = tid >> 3;
    const int sg = tid & 7;

    // ---- Q fragments direct from split gmem ----
    const int qrow0 = q0 + (lane >> 2);
    const int kcol = (lane & 3) * 2;
    uint32_t qh[4][4], ql[4][4];
    {
        const size_t base0 = head_base + (size_t)qrow0 * HD;
        const size_t base1 = base0 + 8 * HD;
        #pragma unroll
        for (int s = 0; s < 4; s++) {
            qh[s][0] = *(const uint32_t*)(g_qh + base0 + s * 16 + kcol);
            qh[s][1] = *(const uint32_t*)(g_qh + base1 + s * 16 + kcol);
            qh[s][2] = *(const uint32_t*)(g_qh + base0 + s * 16 + 8 + kcol);
            qh[s][3] = *(const uint32_t*)(g_qh + base1 + s * 16 + 8 + kcol);
            ql[s][0] = *(const uint32_t*)(g_ql + base0 + s * 16 + kcol);
            ql[s][1] = *(const uint32_t*)(g_ql + base1 + s * 16 + kcol);
            ql[s][2] = *(const uint32_t*)(g_ql + base0 + s * 16 + 8 + kcol);
            ql[s][3] = *(const uint32_t*)(g_ql + base1 + s * 16 + 8 + kcol);
        }
    }

    auto issue = [&](int kt, int bsel) {
        const __nv_bfloat16* s0 = g_kh + head_base + (size_t)kt * 64 * HD;
        const __nv_bfloat16* s1 = g_kl + head_base + (size_t)kt * 64 * HD;
        const __nv_bfloat16* s2 = g_vh + head_base + (size_t)kt * 64 * HD;
        const __nv_bfloat16* s3 = g_vl + head_base + (size_t)kt * 64 * HD;
        const uint32_t db = sb + bsel * ABUFB;
        #pragma unroll
        for (int j = 0; j < 2; j++) {
            int row = srow + j * 32;
            uint32_t doff = (uint32_t)(row * LDV + sg * 8) * 2;
            size_t goff = (size_t)row * HD + sg * 8;
            cp16(db + 0 * VTILEB + doff, s0 + goff);
            cp16(db + 1 * VTILEB + doff, s1 + goff);
            cp16(db + 2 * VTILEB + doff, s2 + goff);
            cp16(db + 3 * VTILEB + doff, s3 + goff);
        }
    };

    float oacc[8][4] = {};
    float l0 = 0.f, l1 = 0.f;

    issue(0, 0); CP_COMMIT();
    issue(1, 1); CP_COMMIT();

    for (int kt = 0; kt < 16; kt++) {
        CP_WAIT1();
        __syncthreads();
        const uint32_t db = sb + (kt & 1) * ABUFB;
        const uint32_t khb = db, klb = db + VTILEB;
        const uint32_t vhb = db + 2 * VTILEB, vlb = db + 3 * VTILEB;

        // ---- S = Q.K^T, exp, pack P ----
        uint32_t pah[4][4], pal[4][4];
        #pragma unroll
        for (int np = 0; np < 4; np++) {
            float sc0[4] = {}, sc1[4] = {};
            #pragma unroll
            for (int s = 0; s < 4; s++) {
                uint32_t off = (uint32_t)((np * 16 + bRow) * LDV + s * 16 + bCol) * 2;
                uint32_t h0, h1, h2, h3, lo0, lo1, lo2, lo3;
                ldm_x4(h0, h1, h2, h3, khb + off);
                ldm_x4(lo0, lo1, lo2, lo3, klb + off);
                uint32_t bh0[2] = {h0, h1}, bh1[2] = {h2, h3};
                uint32_t bl0[2] = {lo0, lo1}, bl1[2] = {lo2, lo3};
                mma_bf16(sc0, qh[s], bh0);
                mma_bf16(sc0, qh[s], bl0);
                mma_bf16(sc0, ql[s], bh0);
                mma_bf16(sc1, qh[s], bh1);
                mma_bf16(sc1, qh[s], bl1);
                mma_bf16(sc1, ql[s], bh1);
            }
            float p00 = __expf(sc0[0] * 0.125f), p01 = __expf(sc0[1] * 0.125f);
            float p02 = __expf(sc0[2] * 0.125f), p03 = __expf(sc0[3] * 0.125f);
            float p10 = __expf(sc1[0] * 0.125f), p11 = __expf(sc1[1] * 0.125f);
            float p12 = __expf(sc1[2] * 0.125f), p13 = __expf(sc1[3] * 0.125f);
            l0 += (p00 + p01) + (p10 + p11);
            l1 += (p02 + p03) + (p12 + p13);
            split2(p00, p01, pah[np][0], pal[np][0]);
            split2(p02, p03, pah[np][1], pal[np][1]);
            split2(p10, p11, pah[np][2], pal[np][2]);
            split2(p12, p13, pah[np][3], pal[np][3]);
        }

        // ---- O += P.V ----
        #pragma unroll
        for (int jn = 0; jn < 4; jn++) {
            #pragma unroll
            for (int s = 0; s < 4; s++) {
                uint32_t off = (uint32_t)((s * 16 + vRow) * LDV + jn * 16 + vCol) * 2;
                uint32_t h0, h1, h2, h3, lo0, lo1, lo2, lo3;
                ldm_x4_t(h0, h1, h2, h3, vhb + off);
                ldm_x4_t(lo0, lo1, lo2, lo3, vlb + off);
                uint32_t bvh0[2] = {h0, h1}, bvh1[2] = {h2, h3};
                uint32_t bvl0[2] = {lo0, lo1}, bvl1[2] = {lo2, lo3};
                mma_bf16(oacc[jn * 2],     pah[s], bvh0);
                mma_bf16(oacc[jn * 2],     pah[s], bvl0);
                mma_bf16(oacc[jn * 2],     pal[s], bvh0);
                mma_bf16(oacc[jn * 2 + 1], pah[s], bvh1);
                mma_bf16(oacc[jn * 2 + 1], pah[s], bvl1);
                mma_bf16(oacc[jn * 2 + 1], pal[s], bvh1);
            }
        }
        __syncthreads();
        if (kt + 2 < 16) issue(kt + 2, kt & 1);
        CP_COMMIT();
    }

    // ---- normalize + split-store o ----
    l0 += __shfl_xor_sync(0xFFFFFFFFu, l0, 1);
    l0 += __shfl_xor_sync(0xFFFFFFFFu, l0, 2);
    l1 += __shfl_xor_sync(0xFFFFFFFFu, l1, 1);
    l1 += __shfl_xor_sync(0xFFFFFFFFu, l1, 2);
    const float inv0 = 1.0f / l0;
    const float inv1 = 1.0f / l1;

    const int b = bh / Hv;
    const int h = bh - b * Hv;
    const int qg0 = blockIdx.x * 128 + wid * 16 + (lane >> 2);
    const size_t o0 = ((size_t)(b * Nv + qg0)) * Cv + h * HD + kcol;
    const size_t o1 = o0 + 8 * (size_t)Cv;
    #pragma unroll
    for (int j = 0; j < 8; j++) {
        uint32_t hh, ll;
        split2(oacc[j][0] * inv0, oacc[j][1] * inv0, hh, ll);
        *(uint32_t*)(g_ohi + o0 + j * 8) = hh;
        *(uint32_t*)(g_olo + o0 + j * 8) = ll;
        split2(oacc[j][2] * inv1, oacc[j][3] * inv1, hh, ll);
        *(uint32_t*)(g_ohi + o1 + j * 8) = hh;
        *(uint32_t*)(g_olo + o1 + j * 8) = ll;
    }
}

// ======================= launch =======================
extern "C" void kernel_launch(void* const* d_in, const int* in_sizes, int n_in,
                              void* d_out, int out_size) {
    const float* x      = (const float*)d_in[0];
    const int*   label  = (const int*)d_in[1];
    const float* alpha  = (const float*)d_in[2];
    const float* qkv_w  = (const float*)d_in[3];
    const float* qkv_b  = (const float*)d_in[4];
    const float* proj_w = (const float*)d_in[5];
    const float* proj_b = (const float*)d_in[6];
    float* out = (float*)d_out;

    cudaFuncSetAttribute(mma_gemm<0>, cudaFuncAttributeMaxDynamicSharedMemorySize, SM_BYTES);
    cudaFuncSetAttribute(mma_gemm<1>, cudaFuncAttributeMaxDynamicSharedMemorySize, SM_BYTES);
    cudaFuncSetAttribute(attn_mma, cudaFuncAttributeMaxDynamicSharedMemorySize, ASM_BYTES);

    gate_kernel<<<(Bv * C3 + 255) / 256, 256>>>(alpha, label);

    split_kernel<0><<<(MT * Cv / 8 + 255) / 256, 256>>>(x, MT * Cv / 8);
    split_kernel<1><<<(C3 * Cv / 8 + 255) / 256, 256>>>(qkv_w, C3 * Cv / 8);
    split_kernel<2><<<(Cv * Cv / 8 + 255) / 256, 256>>>(proj_w, Cv * Cv / 8);

    mma_gemm<0><<<dim3(C3 / 128, MT / 128), 256, SM_BYTES>>>(qkv_b, nullptr);
    attn_mma<<<dim3(Nv / 128, Bv * Hv), 256, ASM_BYTES>>>();
    mma_gemm<1><<<dim3(Cv / 128, MT / 128), 256, SM_BYTES>>>(proj_b, out);
}

// round 8
// speedup vs baseline: 1.1250x; 1.1250x over previous
#include <cuda_runtime.h>
#include <cuda_bf16.h>
#include <cstdint>

#define Bv 16
#define Nv 1024
#define Cv 768
#define Hv 12
#define HD 64
#define C3 2304
#define MT (Bv*Nv)   // 16384

// ======================= device scratch =======================
__device__ float g_sig[Bv * C3];
__device__ __nv_bfloat16 g_xhi[(size_t)MT * Cv],  g_xlo[(size_t)MT * Cv];
__device__ __nv_bfloat16 g_w1hi[(size_t)C3 * Cv], g_w1lo[(size_t)C3 * Cv];
__device__ __nv_bfloat16 g_w2hi[(size_t)Cv * Cv], g_w2lo[(size_t)Cv * Cv];
__device__ __nv_bfloat16 g_qh[(size_t)MT * Cv];                            // (b,h,n,hd) hi only
__device__ __nv_bfloat16 g_kh[(size_t)MT * Cv];                            // hi only
__device__ __nv_bfloat16 g_vh[(size_t)MT * Cv],   g_vl[(size_t)MT * Cv];
__device__ __nv_bfloat16 g_ohi[(size_t)MT * Cv],  g_olo[(size_t)MT * Cv];  // (b,n,c)

// ======================= PTX helpers (baseline ISA only) =======================
__device__ __forceinline__ uint32_t smem_u32(const void* p) {
    uint32_t a;
    asm("{ .reg .u64 t; cvta.to.shared.u64 t, %1; cvt.u32.u64 %0, t; }" : "=r"(a) : "l"(p));
    return a;
}
__device__ __forceinline__ void ldm_x4(uint32_t& r0, uint32_t& r1, uint32_t& r2, uint32_t& r3,
                                       uint32_t addr) {
    asm volatile("ldmatrix.sync.aligned.m8n8.x4.shared.b16 {%0,%1,%2,%3}, [%4];"
                 : "=r"(r0), "=r"(r1), "=r"(r2), "=r"(r3) : "r"(addr));
}
__device__ __forceinline__ void ldm_x4_t(uint32_t& r0, uint32_t& r1, uint32_t& r2, uint32_t& r3,
                                         uint32_t addr) {
    asm volatile("ldmatrix.sync.aligned.m8n8.x4.trans.shared.b16 {%0,%1,%2,%3}, [%4];"
                 : "=r"(r0), "=r"(r1), "=r"(r2), "=r"(r3) : "r"(addr));
}
__device__ __forceinline__ void mma_bf16(float* d, const uint32_t* a, const uint32_t* b) {
    asm volatile(
        "mma.sync.aligned.m16n8k16.row.col.f32.bf16.bf16.f32 "
        "{%0,%1,%2,%3}, {%4,%5,%6,%7}, {%8,%9}, {%0,%1,%2,%3};"
        : "+f"(d[0]), "+f"(d[1]), "+f"(d[2]), "+f"(d[3])
        : "r"(a[0]), "r"(a[1]), "r"(a[2]), "r"(a[3]), "r"(b[0]), "r"(b[1]));
}
__device__ __forceinline__ void cp16(uint32_t dst, const void* src) {
    asm volatile("cp.async.cg.shared.global [%0], [%1], 16;" :: "r"(dst), "l"(src));
}
#define CP_COMMIT() asm volatile("cp.async.commit_group;" ::: "memory")
#define CP_WAIT1()  asm volatile("cp.async.wait_group 1;" ::: "memory")

__device__ __forceinline__ void split8(float4 v0, float4 v1, uint4& hi, uint4& lo) {
    float f[8] = {v0.x, v0.y, v0.z, v0.w, v1.x, v1.y, v1.z, v1.w};
    __nv_bfloat16 h[8], l[8];
    #pragma unroll
    for (int i = 0; i < 8; i++) {
        h[i] = __float2bfloat16(f[i]);
        l[i] = __float2bfloat16(f[i] - __bfloat162float(h[i]));
    }
    hi = *(uint4*)h;
    lo = *(uint4*)l;
}
__device__ __forceinline__ void split2(float x, float y, uint32_t& hi, uint32_t& lo) {
    __nv_bfloat162 h = __floats2bfloat162_rn(x, y);
    __nv_bfloat162 l = __floats2bfloat162_rn(x - __bfloat162float(h.x),
                                             y - __bfloat162float(h.y));
    hi = *(uint32_t*)&h;
    lo = *(uint32_t*)&l;
}

// ======================= gate =======================
__global__ void gate_kernel(const float* __restrict__ alpha,
                            const int* __restrict__ label) {
    int i = blockIdx.x * 256 + threadIdx.x;
    if (i >= Bv * C3) return;
    int b = i / C3;
    int d = i - b * C3;
    float a = alpha[(size_t)label[b] * C3 + d];
    g_sig[i] = 1.0f / (1.0f + __expf(-a));
}

// ======================= fp32 -> bf16 hi/lo split =======================
template<int SEL>
__global__ void split_kernel(const float* __restrict__ src, int n8) {
    int i = blockIdx.x * 256 + threadIdx.x;
    if (i >= n8) return;
    __nv_bfloat16* hi = (SEL == 0) ? g_xhi : (SEL == 1) ? g_w1hi : g_w2hi;
    __nv_bfloat16* lo = (SEL == 0) ? g_xlo : (SEL == 1) ? g_w1lo : g_w2lo;
    const float4* s = (const float4*)src + (size_t)i * 2;
    uint4 h, l;
    split8(s[0], s[1], h, l);
    *(uint4*)(hi + (size_t)i * 8) = h;
    *(uint4*)(lo + (size_t)i * 8) = l;
}

// ======================= split-bf16 HMMA GEMM, K-chunk 32, 2 CTAs/SM =======================
#define LDP 40
#define TILEB (128*LDP*2)           // 10240
#define BUFB  (4*TILEB)             // 40960
#define SM_BYTES (2*BUFB)           // 81920

// EPI 0 = qkv, EPI 1 = proj
template<int EPI>
__global__ __launch_bounds__(256, 2)
void mma_gemm(const float* __restrict__ bias, float* __restrict__ out) {
    extern __shared__ __align__(16) char sm[];
    const uint32_t sb = smem_u32(sm);

    const int tid = threadIdx.x;
    const int wid = tid >> 5;
    const int lane = tid & 31;
    const int m0 = blockIdx.y * 128;
    const int n0 = blockIdx.x * 128;
    const int wm = (wid & 1) * 64;
    const int wn = (wid >> 1) * 32;

    const __nv_bfloat16* Ah = (EPI == 0) ? g_xhi : g_ohi;
    const __nv_bfloat16* Al = (EPI == 0) ? g_xlo : g_olo;
    const __nv_bfloat16* Bh = (EPI == 0) ? g_w1hi : g_w2hi;
    const __nv_bfloat16* Bl = (EPI == 0) ? g_w1lo : g_w2lo;

    const int srow = tid >> 2;
    const int sg = tid & 3;

    const int grp = lane >> 3, lr = lane & 7;
    const int aRow = (grp & 1) * 8 + lr;
    const int aCol = (grp >> 1) * 8;
    const int bRow = (grp >> 1) * 8 + lr;
    const int bCol = (grp & 1) * 8;

    float acc[4][4][4] = {};

    auto issue = [&](int kc, int bsel) {
        const int k0 = kc * 32;
        const __nv_bfloat16* s0 = Ah + (size_t)m0 * Cv + k0;
        const __nv_bfloat16* s1 = Al + (size_t)m0 * Cv + k0;
        const __nv_bfloat16* s2 = Bh + (size_t)n0 * Cv + k0;
        const __nv_bfloat16* s3 = Bl + (size_t)n0 * Cv + k0;
        const uint32_t db = sb + bsel * BUFB;
        #pragma unroll
        for (int j = 0; j < 2; j++) {
            int row = srow + j * 64;
            uint32_t doff = (uint32_t)(row * LDP + sg * 8) * 2;
            size_t goff = (size_t)row * Cv + sg * 8;
            cp16(db + 0 * TILEB + doff, s0 + goff);
            cp16(db + 1 * TILEB + doff, s1 + goff);
            cp16(db + 2 * TILEB + doff, s2 + goff);
            cp16(db + 3 * TILEB + doff, s3 + goff);
        }
    };

    issue(0, 0); CP_COMMIT();
    issue(1, 1); CP_COMMIT();

    for (int kc = 0; kc < 24; kc++) {
        CP_WAIT1();
        __syncthreads();
        const uint32_t db = sb + (kc & 1) * BUFB;

        #pragma unroll
        for (int kk = 0; kk < 2; kk++) {
            uint32_t bh[4][2], bl[4][2];
            #pragma unroll
            for (int np = 0; np < 2; np++) {
                uint32_t off = (uint32_t)((wn + np * 16 + bRow) * LDP + kk * 16 + bCol) * 2;
                uint32_t r0, r1, r2, r3;
                ldm_x4(r0, r1, r2, r3, db + 2 * TILEB + off);
                bh[np * 2][0] = r0; bh[np * 2][1] = r1;
                bh[np * 2 + 1][0] = r2; bh[np * 2 + 1][1] = r3;
                ldm_x4(r0, r1, r2, r3, db + 3 * TILEB + off);
                bl[np * 2][0] = r0; bl[np * 2][1] = r1;
                bl[np * 2 + 1][0] = r2; bl[np * 2 + 1][1] = r3;
            }
            #pragma unroll
            for (int mi = 0; mi < 4; mi++) {
                uint32_t ah[4], al[4];
                uint32_t off = (uint32_t)((wm + mi * 16 + aRow) * LDP + kk * 16 + aCol) * 2;
                ldm_x4(ah[0], ah[1], ah[2], ah[3], db + off);
                ldm_x4(al[0], al[1], al[2], al[3], db + TILEB + off);
                #pragma unroll
                for (int nj = 0; nj < 4; nj++) {
                    mma_bf16(acc[mi][nj], ah, bh[nj]);
                    mma_bf16(acc[mi][nj], ah, bl[nj]);
                    mma_bf16(acc[mi][nj], al, bh[nj]);
                }
            }
        }
        __syncthreads();
        if (kc + 2 < 24) issue(kc + 2, kc & 1);
        CP_COMMIT();
    }

    // ---- epilogue ----
    const int tq = n0 / Cv;
    #pragma unroll
    for (int mi = 0; mi < 4; mi++) {
        #pragma unroll
        for (int nj = 0; nj < 4; nj++) {
            int r = m0 + wm + mi * 16 + (lane >> 2);
            int c = n0 + wn + nj * 8 + 2 * (lane & 3);
            #pragma unroll
            for (int half = 0; half < 2; half++) {
                int rr = r + half * 8;
                float v0 = acc[mi][nj][half * 2 + 0];
                float v1 = acc[mi][nj][half * 2 + 1];
                float2 bi = *(const float2*)(bias + c);
                if (EPI == 0) {
                    int b = rr >> 10;
                    int n = rr & 1023;
                    float2 sg2 = *(const float2*)(g_sig + b * C3 + c);
                    float ox = (v0 + bi.x) * sg2.x;
                    float oy = (v1 + bi.y) * sg2.y;
                    int rem = c - tq * Cv;
                    int h = rem >> 6;
                    int e = rem & 63;
                    size_t idx = ((size_t)(b * Hv + h) * Nv + n) * HD + e;
                    uint32_t hh, ll;
                    split2(ox, oy, hh, ll);
                    if (tq == 0) {
                        *(uint32_t*)(g_qh + idx) = hh;          // q: hi only
                    } else if (tq == 1) {
                        *(uint32_t*)(g_kh + idx) = hh;          // k: hi only
                    } else {
                        *(uint32_t*)(g_vh + idx) = hh;          // v: full split
                        *(uint32_t*)(g_vl + idx) = ll;
                    }
                } else {
                    float2 o;
                    o.x = v0 + bi.x;
                    o.y = v1 + bi.y;
                    *(float2*)(out + (size_t)rr * Cv + c) = o;
                }
            }
        }
    }
}

// ======================= HMMA flash attention: bf16 QK^T, split-bf16 PV =======================
#define LDV 72
#define VTILEB (64*LDV*2)           // 9216
#define ABUFB (3*VTILEB)            // KH, VH, VL = 27648
#define ASM_BYTES (2*ABUFB)         // 55296

__global__ __launch_bounds__(256, 2) void attn_mma() {
    extern __shared__ __align__(16) char sm[];
    const uint32_t sb = smem_u32(sm);

    const int tid = threadIdx.x;
    const int wid = tid >> 5;
    const int lane = tid & 31;
    const int bh = blockIdx.y;
    const size_t head_base = (size_t)bh * Nv * HD;
    const int q0 = blockIdx.x * 128 + wid * 16;

    const int grp = lane >> 3, lr = lane & 7;
    const int bRow = (grp >> 1) * 8 + lr;
    const int bCol = (grp & 1) * 8;
    const int vRow = lane & 15;
    const int vCol = (lane >> 4) * 8;

    const int srow = tid >> 3;
    const int sg = tid & 7;

    // ---- Q fragments (hi only) direct from gmem ----
    const int qrow0 = q0 + (lane >> 2);
    const int kcol = (lane & 3) * 2;
    uint32_t qh[4][4];
    {
        const size_t base0 = head_base + (size_t)qrow0 * HD;
        const size_t base1 = base0 + 8 * HD;
        #pragma unroll
        for (int s = 0; s < 4; s++) {
            qh[s][0] = *(const uint32_t*)(g_qh + base0 + s * 16 + kcol);
            qh[s][1] = *(const uint32_t*)(g_qh + base1 + s * 16 + kcol);
            qh[s][2] = *(const uint32_t*)(g_qh + base0 + s * 16 + 8 + kcol);
            qh[s][3] = *(const uint32_t*)(g_qh + base1 + s * 16 + 8 + kcol);
        }
    }

    auto issue = [&](int kt, int bsel) {
        const __nv_bfloat16* s0 = g_kh + head_base + (size_t)kt * 64 * HD;
        const __nv_bfloat16* s2 = g_vh + head_base + (size_t)kt * 64 * HD;
        const __nv_bfloat16* s3 = g_vl + head_base + (size_t)kt * 64 * HD;
        const uint32_t db = sb + bsel * ABUFB;
        #pragma unroll
        for (int j = 0; j < 2; j++) {
            int row = srow + j * 32;
            uint32_t doff = (uint32_t)(row * LDV + sg * 8) * 2;
            size_t goff = (size_t)row * HD + sg * 8;
            cp16(db + 0 * VTILEB + doff, s0 + goff);
            cp16(db + 1 * VTILEB + doff, s2 + goff);
            cp16(db + 2 * VTILEB + doff, s3 + goff);
        }
    };

    float oacc[8][4] = {};
    float l0 = 0.f, l1 = 0.f;

    issue(0, 0); CP_COMMIT();
    issue(1, 1); CP_COMMIT();

    for (int kt = 0; kt < 16; kt++) {
        CP_WAIT1();
        __syncthreads();
        const uint32_t db = sb + (kt & 1) * ABUFB;
        const uint32_t khb = db;
        const uint32_t vhb = db + 1 * VTILEB, vlb = db + 2 * VTILEB;

        // ---- S = Q.K^T (bf16 hi only), exp, pack P ----
        uint32_t pah[4][4], pal[4][4];
        #pragma unroll
        for (int np = 0; np < 4; np++) {
            float sc0[4] = {}, sc1[4] = {};
            #pragma unroll
            for (int s = 0; s < 4; s++) {
                uint32_t off = (uint32_t)((np * 16 + bRow) * LDV + s * 16 + bCol) * 2;
                uint32_t h0, h1, h2, h3;
                ldm_x4(h0, h1, h2, h3, khb + off);
                uint32_t bh0[2] = {h0, h1}, bh1[2] = {h2, h3};
                mma_bf16(sc0, qh[s], bh0);
                mma_bf16(sc1, qh[s], bh1);
            }
            float p00 = __expf(sc0[0] * 0.125f), p01 = __expf(sc0[1] * 0.125f);
            float p02 = __expf(sc0[2] * 0.125f), p03 = __expf(sc0[3] * 0.125f);
            float p10 = __expf(sc1[0] * 0.125f), p11 = __expf(sc1[1] * 0.125f);
            float p12 = __expf(sc1[2] * 0.125f), p13 = __expf(sc1[3] * 0.125f);
            l0 += (p00 + p01) + (p10 + p11);
            l1 += (p02 + p03) + (p12 + p13);
            split2(p00, p01, pah[np][0], pal[np][0]);
            split2(p02, p03, pah[np][1], pal[np][1]);
            split2(p10, p11, pah[np][2], pal[np][2]);
            split2(p12, p13, pah[np][3], pal[np][3]);
        }

        // ---- O += P.V (3-MMA split) ----
        #pragma unroll
        for (int jn = 0; jn < 4; jn++) {
            #pragma unroll
            for (int s = 0; s < 4; s++) {
                uint32_t off = (uint32_t)((s * 16 + vRow) * LDV + jn * 16 + vCol) * 2;
                uint32_t h0, h1, h2, h3, lo0, lo1, lo2, lo3;
                ldm_x4_t(h0, h1, h2, h3, vhb + off);
                ldm_x4_t(lo0, lo1, lo2, lo3, vlb + off);
                uint32_t bvh0[2] = {h0, h1}, bvh1[2] = {h2, h3};
                uint32_t bvl0[2] = {lo0, lo1}, bvl1[2] = {lo2, lo3};
                mma_bf16(oacc[jn * 2],     pah[s], bvh0);
                mma_bf16(oacc[jn * 2],     pah[s], bvl0);
                mma_bf16(oacc[jn * 2],     pal[s], bvh0);
                mma_bf16(oacc[jn * 2 + 1], pah[s], bvh1);
                mma_bf16(oacc[jn * 2 + 1], pah[s], bvl1);
                mma_bf16(oacc[jn * 2 + 1], pal[s], bvh1);
            }
        }
        __syncthreads();
        if (kt + 2 < 16) issue(kt + 2, kt & 1);
        CP_COMMIT();
    }

    // ---- normalize + split-store o ----
    l0 += __shfl_xor_sync(0xFFFFFFFFu, l0, 1);
    l0 += __shfl_xor_sync(0xFFFFFFFFu, l0, 2);
    l1 += __shfl_xor_sync(0xFFFFFFFFu, l1, 1);
    l1 += __shfl_xor_sync(0xFFFFFFFFu, l1, 2);
    const float inv0 = 1.0f / l0;
    const float inv1 = 1.0f / l1;

    const int b = bh / Hv;
    const int h = bh - b * Hv;
    const int qg0 = blockIdx.x * 128 + wid * 16 + (lane >> 2);
    const size_t o0 = ((size_t)(b * Nv + qg0)) * Cv + h * HD + kcol;
    const size_t o1 = o0 + 8 * (size_t)Cv;
    #pragma unroll
    for (int j = 0; j < 8; j++) {
        uint32_t hh, ll;
        split2(oacc[j][0] * inv0, oacc[j][1] * inv0, hh, ll);
        *(uint32_t*)(g_ohi + o0 + j * 8) = hh;
        *(uint32_t*)(g_olo + o0 + j * 8) = ll;
        split2(oacc[j][2] * inv1, oacc[j][3] * inv1, hh, ll);
        *(uint32_t*)(g_ohi + o1 + j * 8) = hh;
        *(uint32_t*)(g_olo + o1 + j * 8) = ll;
    }
}

// ======================= launch =======================
extern "C" void kernel_launch(void* const* d_in, const int* in_sizes, int n_in,
                              void* d_out, int out_size) {
    const float* x      = (const float*)d_in[0];
    const int*   label  = (const int*)d_in[1];
    const float* alpha  = (const float*)d_in[2];
    const float* qkv_w  = (const float*)d_in[3];
    const float* qkv_b  = (const float*)d_in[4];
    const float* proj_w = (const float*)d_in[5];
    const float* proj_b = (const float*)d_in[6];
    float* out = (float*)d_out;

    cudaFuncSetAttribute(mma_gemm<0>, cudaFuncAttributeMaxDynamicSharedMemorySize, SM_BYTES);
    cudaFuncSetAttribute(mma_gemm<1>, cudaFuncAttributeMaxDynamicSharedMemorySize, SM_BYTES);
    cudaFuncSetAttribute(attn_mma, cudaFuncAttributeMaxDynamicSharedMemorySize, ASM_BYTES);

    gate_kernel<<<(Bv * C3 + 255) / 256, 256>>>(alpha, label);

    split_kernel<0><<<(MT * Cv / 8 + 255) / 256, 256>>>(x, MT * Cv / 8);
    split_kernel<1><<<(C3 * Cv / 8 + 255) / 256, 256>>>(qkv_w, C3 * Cv / 8);
    split_kernel<2><<<(Cv * Cv / 8 + 255) / 256, 256>>>(proj_w, Cv * Cv / 8);

    mma_gemm<0><<<dim3(C3 / 128, MT / 128), 256, SM_BYTES>>>(qkv_b, nullptr);
    attn_mma<<<dim3(Nv / 128, Bv * Hv), 256, ASM_BYTES>>>();
    mma_gemm<1><<<dim3(Cv / 128, MT / 128), 256, SM_BYTES>>>(proj_b, out);
}

// round 9
// speedup vs baseline: 1.6760x; 1.4898x over previous
#include <cuda_runtime.h>
#include <cuda_fp16.h>
#include <cstdint>

#define Bv 16
#define Nv 1024
#define Cv 768
#define Hv 12
#define HD 64
#define C3 2304
#define MT (Bv*Nv)   // 16384

// ======================= device scratch =======================
__device__ float g_sig[Bv * C3];
__device__ __half g_xhi[(size_t)MT * Cv], g_xlo[(size_t)MT * Cv];
__device__ __half g_w1h[(size_t)C3 * Cv];
__device__ __half g_w2h[(size_t)Cv * Cv];
__device__ __half g_qh[(size_t)MT * Cv];                         // (b,h,n,hd) fp16
__device__ __half g_kh[(size_t)MT * Cv];
__device__ __half g_vh[(size_t)MT * Cv];
__device__ __half g_ohi[(size_t)MT * Cv], g_olo[(size_t)MT * Cv]; // (b,n,c) split

// ======================= PTX helpers (baseline ISA only) =======================
__device__ __forceinline__ uint32_t smem_u32(const void* p) {
    uint32_t a;
    asm("{ .reg .u64 t; cvta.to.shared.u64 t, %1; cvt.u32.u64 %0, t; }" : "=r"(a) : "l"(p));
    return a;
}
__device__ __forceinline__ void ldm_x4(uint32_t& r0, uint32_t& r1, uint32_t& r2, uint32_t& r3,
                                       uint32_t addr) {
    asm volatile("ldmatrix.sync.aligned.m8n8.x4.shared.b16 {%0,%1,%2,%3}, [%4];"
                 : "=r"(r0), "=r"(r1), "=r"(r2), "=r"(r3) : "r"(addr));
}
__device__ __forceinline__ void ldm_x4_t(uint32_t& r0, uint32_t& r1, uint32_t& r2, uint32_t& r3,
                                         uint32_t addr) {
    asm volatile("ldmatrix.sync.aligned.m8n8.x4.trans.shared.b16 {%0,%1,%2,%3}, [%4];"
                 : "=r"(r0), "=r"(r1), "=r"(r2), "=r"(r3) : "r"(addr));
}
__device__ __forceinline__ void mma_f16(float* d, const uint32_t* a, const uint32_t* b) {
    asm volatile(
        "mma.sync.aligned.m16n8k16.row.col.f32.f16.f16.f32 "
        "{%0,%1,%2,%3}, {%4,%5,%6,%7}, {%8,%9}, {%0,%1,%2,%3};"
        : "+f"(d[0]), "+f"(d[1]), "+f"(d[2]), "+f"(d[3])
        : "r"(a[0]), "r"(a[1]), "r"(a[2]), "r"(a[3]), "r"(b[0]), "r"(b[1]));
}
__device__ __forceinline__ void cp16(uint32_t dst, const void* src) {
    asm volatile("cp.async.cg.shared.global [%0], [%1], 16;" :: "r"(dst), "l"(src));
}
#define CP_COMMIT() asm volatile("cp.async.commit_group;" ::: "memory")
#define CP_WAIT1()  asm volatile("cp.async.wait_group 1;" ::: "memory")

__device__ __forceinline__ void split8h(float4 v0, float4 v1, uint4& hi, uint4& lo) {
    float f[8] = {v0.x, v0.y, v0.z, v0.w, v1.x, v1.y, v1.z, v1.w};
    __half h[8], l[8];
    #pragma unroll
    for (int i = 0; i < 8; i++) {
        h[i] = __float2half_rn(f[i]);
        l[i] = __float2half_rn(f[i] - __half2float(h[i]));
    }
    hi = *(uint4*)h;
    lo = *(uint4*)l;
}
__device__ __forceinline__ uint32_t pack2h(float x, float y) {
    __half2 h = __floats2half2_rn(x, y);
    return *(uint32_t*)&h;
}
__device__ __forceinline__ void split2h(float x, float y, uint32_t& hi, uint32_t& lo) {
    __half2 h = __floats2half2_rn(x, y);
    __half2 l = __floats2half2_rn(x - __half2float(h.x), y - __half2float(h.y));
    hi = *(uint32_t*)&h;
    lo = *(uint32_t*)&l;
}

// ======================= gate =======================
__global__ void gate_kernel(const float* __restrict__ alpha,
                            const int* __restrict__ label) {
    int i = blockIdx.x * 256 + threadIdx.x;
    if (i >= Bv * C3) return;
    int b = i / C3;
    int d = i - b * C3;
    float a = alpha[(size_t)label[b] * C3 + d];
    g_sig[i] = 1.0f / (1.0f + __expf(-a));
}

// ======================= fp32 -> fp16 split / convert =======================
// SEL 0: x -> hi+lo.  SEL 1: w1 -> hi only.  SEL 2: w2 -> hi only.
template<int SEL>
__global__ void split_kernel(const float* __restrict__ src, int n8) {
    int i = blockIdx.x * 256 + threadIdx.x;
    if (i >= n8) return;
    const float4* s = (const float4*)src + (size_t)i * 2;
    uint4 h, l;
    split8h(s[0], s[1], h, l);
    if (SEL == 0) {
        *(uint4*)(g_xhi + (size_t)i * 8) = h;
        *(uint4*)(g_xlo + (size_t)i * 8) = l;
    } else if (SEL == 1) {
        *(uint4*)(g_w1h + (size_t)i * 8) = h;
    } else {
        *(uint4*)(g_w2h + (size_t)i * 8) = h;
    }
}

// ======================= fp16 HMMA GEMM: A split (hi+lo), B hi; 2 MMAs =======================
#define LDP 40
#define TILEB (128*LDP*2)           // 10240
#define BUFB  (3*TILEB)             // AH, AL, BH = 30720
#define SM_BYTES (2*BUFB)           // 61440 -> 2 CTAs/SM

// EPI 0 = qkv (A=x, B=w1h, gated scatter -> q/k/v fp16), EPI 1 = proj (A=o, B=w2h, bias -> out)
template<int EPI>
__global__ __launch_bounds__(256, 2)
void mma_gemm(const float* __restrict__ bias, float* __restrict__ out) {
    extern __shared__ __align__(16) char sm[];
    const uint32_t sb = smem_u32(sm);

    const int tid = threadIdx.x;
    const int wid = tid >> 5;
    const int lane = tid & 31;
    const int m0 = blockIdx.y * 128;
    const int n0 = blockIdx.x * 128;
    const int wm = (wid & 1) * 64;
    const int wn = (wid >> 1) * 32;

    const __half* Ah = (EPI == 0) ? g_xhi : g_ohi;
    const __half* Al = (EPI == 0) ? g_xlo : g_olo;
    const __half* Bh = (EPI == 0) ? g_w1h : g_w2h;

    const int srow = tid >> 2;
    const int sg = tid & 3;

    const int grp = lane >> 3, lr = lane & 7;
    const int aRow = (grp & 1) * 8 + lr;
    const int aCol = (grp >> 1) * 8;
    const int bRow = (grp >> 1) * 8 + lr;
    const int bCol = (grp & 1) * 8;

    float acc[4][4][4] = {};

    auto issue = [&](int kc, int bsel) {
        const int k0 = kc * 32;
        const __half* s0 = Ah + (size_t)m0 * Cv + k0;
        const __half* s1 = Al + (size_t)m0 * Cv + k0;
        const __half* s2 = Bh + (size_t)n0 * Cv + k0;
        const uint32_t db = sb + bsel * BUFB;
        #pragma unroll
        for (int j = 0; j < 2; j++) {
            int row = srow + j * 64;
            uint32_t doff = (uint32_t)(row * LDP + sg * 8) * 2;
            size_t goff = (size_t)row * Cv + sg * 8;
            cp16(db + 0 * TILEB + doff, s0 + goff);
            cp16(db + 1 * TILEB + doff, s1 + goff);
            cp16(db + 2 * TILEB + doff, s2 + goff);
        }
    };

    issue(0, 0); CP_COMMIT();
    issue(1, 1); CP_COMMIT();

    for (int kc = 0; kc < 24; kc++) {
        CP_WAIT1();
        __syncthreads();
        const uint32_t db = sb + (kc & 1) * BUFB;

        #pragma unroll
        for (int kk = 0; kk < 2; kk++) {
            uint32_t bh[4][2];
            #pragma unroll
            for (int np = 0; np < 2; np++) {
                uint32_t off = (uint32_t)((wn + np * 16 + bRow) * LDP + kk * 16 + bCol) * 2;
                uint32_t r0, r1, r2, r3;
                ldm_x4(r0, r1, r2, r3, db + 2 * TILEB + off);
                bh[np * 2][0] = r0; bh[np * 2][1] = r1;
                bh[np * 2 + 1][0] = r2; bh[np * 2 + 1][1] = r3;
            }
            #pragma unroll
            for (int mi = 0; mi < 4; mi++) {
                uint32_t ah[4], al[4];
                uint32_t off = (uint32_t)((wm + mi * 16 + aRow) * LDP + kk * 16 + aCol) * 2;
                ldm_x4(ah[0], ah[1], ah[2], ah[3], db + off);
                ldm_x4(al[0], al[1], al[2], al[3], db + TILEB + off);
                #pragma unroll
                for (int nj = 0; nj < 4; nj++) {
                    mma_f16(acc[mi][nj], ah, bh[nj]);
                    mma_f16(acc[mi][nj], al, bh[nj]);
                }
            }
        }
        __syncthreads();
        if (kc + 2 < 24) issue(kc + 2, kc & 1);
        CP_COMMIT();
    }

    // ---- epilogue ----
    const int tq = n0 / Cv;
    #pragma unroll
    for (int mi = 0; mi < 4; mi++) {
        #pragma unroll
        for (int nj = 0; nj < 4; nj++) {
            int r = m0 + wm + mi * 16 + (lane >> 2);
            int c = n0 + wn + nj * 8 + 2 * (lane & 3);
            #pragma unroll
            for (int half = 0; half < 2; half++) {
                int rr = r + half * 8;
                float v0 = acc[mi][nj][half * 2 + 0];
                float v1 = acc[mi][nj][half * 2 + 1];
                float2 bi = *(const float2*)(bias + c);
                if (EPI == 0) {
                    int b = rr >> 10;
                    int n = rr & 1023;
                    float2 sg2 = *(const float2*)(g_sig + b * C3 + c);
                    float ox = (v0 + bi.x) * sg2.x;
                    float oy = (v1 + bi.y) * sg2.y;
                    int rem = c - tq * Cv;
                    int h = rem >> 6;
                    int e = rem & 63;
                    size_t idx = ((size_t)(b * Hv + h) * Nv + n) * HD + e;
                    uint32_t hh = pack2h(ox, oy);
                    __half* dst = (tq == 0) ? g_qh : (tq == 1) ? g_kh : g_vh;
                    *(uint32_t*)(dst + idx) = hh;
                } else {
                    float2 o;
                    o.x = v0 + bi.x;
                    o.y = v1 + bi.y;
                    *(float2*)(out + (size_t)rr * Cv + c) = o;
                }
            }
        }
    }
}

// ======================= fp16 HMMA flash attention: 1-MMA QK^T, 1-MMA PV =======================
#define LDV 72
#define VTILEB (64*LDV*2)           // 9216
#define ABUFB (2*VTILEB)            // KH, VH = 18432
#define ASM_BYTES (2*ABUFB)         // 36864

__global__ __launch_bounds__(256, 2) void attn_mma() {
    extern __shared__ __align__(16) char sm[];
    const uint32_t sb = smem_u32(sm);

    const int tid = threadIdx.x;
    const int wid = tid >> 5;
    const int lane = tid & 31;
    const int bh = blockIdx.y;
    const size_t head_base = (size_t)bh * Nv * HD;
    const int q0 = blockIdx.x * 128 + wid * 16;

    const int grp = lane >> 3, lr = lane & 7;
    const int bRow = (grp >> 1) * 8 + lr;
    const int bCol = (grp & 1) * 8;
    const int vRow = lane & 15;
    const int vCol = (lane >> 4) * 8;

    const int srow = tid >> 3;
    const int sg = tid & 7;

    // ---- Q fragments (fp16) direct from gmem ----
    const int qrow0 = q0 + (lane >> 2);
    const int kcol = (lane & 3) * 2;
    uint32_t qh[4][4];
    {
        const size_t base0 = head_base + (size_t)qrow0 * HD;
        const size_t base1 = base0 + 8 * HD;
        #pragma unroll
        for (int s = 0; s < 4; s++) {
            qh[s][0] = *(const uint32_t*)(g_qh + base0 + s * 16 + kcol);
            qh[s][1] = *(const uint32_t*)(g_qh + base1 + s * 16 + kcol);
            qh[s][2] = *(const uint32_t*)(g_qh + base0 + s * 16 + 8 + kcol);
            qh[s][3] = *(const uint32_t*)(g_qh + base1 + s * 16 + 8 + kcol);
        }
    }

    auto issue = [&](int kt, int bsel) {
        const __half* s0 = g_kh + head_base + (size_t)kt * 64 * HD;
        const __half* s1 = g_vh + head_base + (size_t)kt * 64 * HD;
        const uint32_t db = sb + bsel * ABUFB;
        #pragma unroll
        for (int j = 0; j < 2; j++) {
            int row = srow + j * 32;
            uint32_t doff = (uint32_t)(row * LDV + sg * 8) * 2;
            size_t goff = (size_t)row * HD + sg * 8;
            cp16(db + 0 * VTILEB + doff, s0 + goff);
            cp16(db + 1 * VTILEB + doff, s1 + goff);
        }
    };

    float oacc[8][4] = {};
    float l0 = 0.f, l1 = 0.f;

    issue(0, 0); CP_COMMIT();
    issue(1, 1); CP_COMMIT();

    for (int kt = 0; kt < 16; kt++) {
        CP_WAIT1();
        __syncthreads();
        const uint32_t db = sb + (kt & 1) * ABUFB;
        const uint32_t khb = db;
        const uint32_t vhb = db + VTILEB;

        // ---- S = Q.K^T (fp16), exp, pack P (plain fp16) ----
        uint32_t pa[4][4];
        #pragma unroll
        for (int np = 0; np < 4; np++) {
            float sc0[4] = {}, sc1[4] = {};
            #pragma unroll
            for (int s = 0; s < 4; s++) {
                uint32_t off = (uint32_t)((np * 16 + bRow) * LDV + s * 16 + bCol) * 2;
                uint32_t h0, h1, h2, h3;
                ldm_x4(h0, h1, h2, h3, khb + off);
                uint32_t bh0[2] = {h0, h1}, bh1[2] = {h2, h3};
                mma_f16(sc0, qh[s], bh0);
                mma_f16(sc1, qh[s], bh1);
            }
            float p00 = __expf(sc0[0] * 0.125f), p01 = __expf(sc0[1] * 0.125f);
            float p02 = __expf(sc0[2] * 0.125f), p03 = __expf(sc0[3] * 0.125f);
            float p10 = __expf(sc1[0] * 0.125f), p11 = __expf(sc1[1] * 0.125f);
            float p12 = __expf(sc1[2] * 0.125f), p13 = __expf(sc1[3] * 0.125f);
            l0 += (p00 + p01) + (p10 + p11);
            l1 += (p02 + p03) + (p12 + p13);
            pa[np][0] = pack2h(p00, p01);
            pa[np][1] = pack2h(p02, p03);
            pa[np][2] = pack2h(p10, p11);
            pa[np][3] = pack2h(p12, p13);
        }

        // ---- O += P.V (1 MMA) ----
        #pragma unroll
        for (int jn = 0; jn < 4; jn++) {
            #pragma unroll
            for (int s = 0; s < 4; s++) {
                uint32_t off = (uint32_t)((s * 16 + vRow) * LDV + jn * 16 + vCol) * 2;
                uint32_t h0, h1, h2, h3;
                ldm_x4_t(h0, h1, h2, h3, vhb + off);
                uint32_t bvh0[2] = {h0, h1}, bvh1[2] = {h2, h3};
                mma_f16(oacc[jn * 2],     pa[s], bvh0);
                mma_f16(oacc[jn * 2 + 1], pa[s], bvh1);
            }
        }
        __syncthreads();
        if (kt + 2 < 16) issue(kt + 2, kt & 1);
        CP_COMMIT();
    }

    // ---- normalize + split-store o (hi+lo for proj) ----
    l0 += __shfl_xor_sync(0xFFFFFFFFu, l0, 1);
    l0 += __shfl_xor_sync(0xFFFFFFFFu, l0, 2);
    l1 += __shfl_xor_sync(0xFFFFFFFFu, l1, 1);
    l1 += __shfl_xor_sync(0xFFFFFFFFu, l1, 2);
    const float inv0 = 1.0f / l0;
    const float inv1 = 1.0f / l1;

    const int b = bh / Hv;
    const int h = bh - b * Hv;
    const int qg0 = blockIdx.x * 128 + wid * 16 + (lane >> 2);
    const size_t o0 = ((size_t)(b * Nv + qg0)) * Cv + h * HD + kcol;
    const size_t o1 = o0 + 8 * (size_t)Cv;
    #pragma unroll
    for (int j = 0; j < 8; j++) {
        uint32_t hh, ll;
        split2h(oacc[j][0] * inv0, oacc[j][1] * inv0, hh, ll);
        *(uint32_t*)(g_ohi + o0 + j * 8) = hh;
        *(uint32_t*)(g_olo + o0 + j * 8) = ll;
        split2h(oacc[j][2] * inv1, oacc[j][3] * inv1, hh, ll);
        *(uint32_t*)(g_ohi + o1 + j * 8) = hh;
        *(uint32_t*)(g_olo + o1 + j * 8) = ll;
    }
}

// ======================= launch =======================
extern "C" void kernel_launch(void* const* d_in, const int* in_sizes, int n_in,
                              void* d_out, int out_size) {
    const float* x      = (const float*)d_in[0];
    const int*   label  = (const int*)d_in[1];
    const float* alpha  = (const float*)d_in[2];
    const float* qkv_w  = (const float*)d_in[3];
    const float* qkv_b  = (const float*)d_in[4];
    const float* proj_w = (const float*)d_in[5];
    const float* proj_b = (const float*)d_in[6];
    float* out = (float*)d_out;

    cudaFuncSetAttribute(mma_gemm<0>, cudaFuncAttributeMaxDynamicSharedMemorySize, SM_BYTES);
    cudaFuncSetAttribute(mma_gemm<1>, cudaFuncAttributeMaxDynamicSharedMemorySize, SM_BYTES);
    cudaFuncSetAttribute(attn_mma, cudaFuncAttributeMaxDynamicSharedMemorySize, ASM_BYTES);

    gate_kernel<<<(Bv * C3 + 255) / 256, 256>>>(alpha, label);

    split_kernel<0><<<(MT * Cv / 8 + 255) / 256, 256>>>(x, MT * Cv / 8);
    split_kernel<1><<<(C3 * Cv / 8 + 255) / 256, 256>>>(qkv_w, C3 * Cv / 8);
    split_kernel<2><<<(Cv * Cv / 8 + 255) / 256, 256>>>(proj_w, Cv * Cv / 8);

    mma_gemm<0><<<dim3(C3 / 128, MT / 128), 256, SM_BYTES>>>(qkv_b, nullptr);
    attn_mma<<<dim3(Nv / 128, Bv * Hv), 256, ASM_BYTES>>>();
    mma_gemm<1><<<dim3(Cv / 128, MT / 128), 256, SM_BYTES>>>(proj_b, out);
}

// round 10
// speedup vs baseline: 2.4840x; 1.4821x over previous
#include <cuda_runtime.h>
#include <cuda_fp16.h>
#include <cstdint>

#define Bv 16
#define Nv 1024
#define Cv 768
#define Hv 12
#define HD 64
#define C3 2304
#define MT (Bv*Nv)   // 16384

// ======================= device scratch =======================
__device__ float g_sig[Bv * C3];
__device__ __half g_xh[(size_t)MT * Cv];
__device__ __half g_w1h[(size_t)C3 * Cv];
__device__ __half g_w2h[(size_t)Cv * Cv];
__device__ __half g_qh[(size_t)MT * Cv];   // (b,h,n,hd) fp16
__device__ __half g_kh[(size_t)MT * Cv];
__device__ __half g_vh[(size_t)MT * Cv];
__device__ __half g_oh[(size_t)MT * Cv];   // (b,n,c) fp16

// ======================= PTX helpers (baseline ISA only) =======================
__device__ __forceinline__ uint32_t smem_u32(const void* p) {
    uint32_t a;
    asm("{ .reg .u64 t; cvta.to.shared.u64 t, %1; cvt.u32.u64 %0, t; }" : "=r"(a) : "l"(p));
    return a;
}
__device__ __forceinline__ void ldm_x4(uint32_t& r0, uint32_t& r1, uint32_t& r2, uint32_t& r3,
                                       uint32_t addr) {
    asm volatile("ldmatrix.sync.aligned.m8n8.x4.shared.b16 {%0,%1,%2,%3}, [%4];"
                 : "=r"(r0), "=r"(r1), "=r"(r2), "=r"(r3) : "r"(addr));
}
__device__ __forceinline__ void ldm_x4_t(uint32_t& r0, uint32_t& r1, uint32_t& r2, uint32_t& r3,
                                         uint32_t addr) {
    asm volatile("ldmatrix.sync.aligned.m8n8.x4.trans.shared.b16 {%0,%1,%2,%3}, [%4];"
                 : "=r"(r0), "=r"(r1), "=r"(r2), "=r"(r3) : "r"(addr));
}
__device__ __forceinline__ void mma_f16(float* d, const uint32_t* a, const uint32_t* b) {
    asm volatile(
        "mma.sync.aligned.m16n8k16.row.col.f32.f16.f16.f32 "
        "{%0,%1,%2,%3}, {%4,%5,%6,%7}, {%8,%9}, {%0,%1,%2,%3};"
        : "+f"(d[0]), "+f"(d[1]), "+f"(d[2]), "+f"(d[3])
        : "r"(a[0]), "r"(a[1]), "r"(a[2]), "r"(a[3]), "r"(b[0]), "r"(b[1]));
}
__device__ __forceinline__ void cp16(uint32_t dst, const void* src) {
    asm volatile("cp.async.cg.shared.global [%0], [%1], 16;" :: "r"(dst), "l"(src));
}
#define CP_COMMIT() asm volatile("cp.async.commit_group;" ::: "memory")
#define CP_WAIT1()  asm volatile("cp.async.wait_group 1;" ::: "memory")

__device__ __forceinline__ uint32_t pack2h(float x, float y) {
    __half2 h = __floats2half2_rn(x, y);
    return *(uint32_t*)&h;
}

// ======================= gate =======================
__global__ void gate_kernel(const float* __restrict__ alpha,
                            const int* __restrict__ label) {
    int i = blockIdx.x * 256 + threadIdx.x;
    if (i >= Bv * C3) return;
    int b = i / C3;
    int d = i - b * C3;
    float a = alpha[(size_t)label[b] * C3 + d];
    g_sig[i] = 1.0f / (1.0f + __expf(-a));
}

// ======================= fp32 -> fp16 convert =======================
// SEL 0: x, 1: w1, 2: w2
template<int SEL>
__global__ void cvt_kernel(const float* __restrict__ src, int n8) {
    int i = blockIdx.x * 256 + threadIdx.x;
    if (i >= n8) return;
    const float4* s = (const float4*)src + (size_t)i * 2;
    float4 v0 = s[0], v1 = s[1];
    __half h[8] = {
        __float2half_rn(v0.x), __float2half_rn(v0.y), __float2half_rn(v0.z), __float2half_rn(v0.w),
        __float2half_rn(v1.x), __float2half_rn(v1.y), __float2half_rn(v1.z), __float2half_rn(v1.w)
    };
    __half* dst = (SEL == 0) ? g_xh : (SEL == 1) ? g_w1h : g_w2h;
    *(uint4*)(dst + (size_t)i * 8) = *(uint4*)h;
}

// ======================= fp16 HMMA GEMM: 1 MMA per k16 =======================
#define LDP 40
#define TILEB (128*LDP*2)           // 10240
#define BUFB  (2*TILEB)             // A, B = 20480
#define SM_BYTES (2*BUFB)           // 40960 -> 2 CTAs/SM

// EPI 0 = qkv (A=xh, B=w1h, gated scatter -> q/k/v fp16), EPI 1 = proj (A=oh, B=w2h, bias -> out)
template<int EPI>
__global__ __launch_bounds__(256, 2)
void mma_gemm(const float* __restrict__ bias, float* __restrict__ out) {
    extern __shared__ __align__(16) char sm[];
    const uint32_t sb = smem_u32(sm);

    const int tid = threadIdx.x;
    const int wid = tid >> 5;
    const int lane = tid & 31;
    const int m0 = blockIdx.y * 128;
    const int n0 = blockIdx.x * 128;
    const int wm = (wid & 1) * 64;
    const int wn = (wid >> 1) * 32;

    const __half* Ah = (EPI == 0) ? g_xh : g_oh;
    const __half* Bh = (EPI == 0) ? g_w1h : g_w2h;

    const int srow = tid >> 2;
    const int sg = tid & 3;

    const int grp = lane >> 3, lr = lane & 7;
    const int aRow = (grp & 1) * 8 + lr;
    const int aCol = (grp >> 1) * 8;
    const int bRow = (grp >> 1) * 8 + lr;
    const int bCol = (grp & 1) * 8;

    float acc[4][4][4] = {};

    auto issue = [&](int kc, int bsel) {
        const int k0 = kc * 32;
        const __half* s0 = Ah + (size_t)m0 * Cv + k0;
        const __half* s1 = Bh + (size_t)n0 * Cv + k0;
        const uint32_t db = sb + bsel * BUFB;
        #pragma unroll
        for (int j = 0; j < 2; j++) {
            int row = srow + j * 64;
            uint32_t doff = (uint32_t)(row * LDP + sg * 8) * 2;
            size_t goff = (size_t)row * Cv + sg * 8;
            cp16(db + 0 * TILEB + doff, s0 + goff);
            cp16(db + 1 * TILEB + doff, s1 + goff);
        }
    };

    issue(0, 0); CP_COMMIT();
    issue(1, 1); CP_COMMIT();

    for (int kc = 0; kc < 24; kc++) {
        CP_WAIT1();
        __syncthreads();
        const uint32_t db = sb + (kc & 1) * BUFB;

        #pragma unroll
        for (int kk = 0; kk < 2; kk++) {
            uint32_t bh[4][2];
            #pragma unroll
            for (int np = 0; np < 2; np++) {
                uint32_t off = (uint32_t)((wn + np * 16 + bRow) * LDP + kk * 16 + bCol) * 2;
                uint32_t r0, r1, r2, r3;
                ldm_x4(r0, r1, r2, r3, db + TILEB + off);
                bh[np * 2][0] = r0; bh[np * 2][1] = r1;
                bh[np * 2 + 1][0] = r2; bh[np * 2 + 1][1] = r3;
            }
            #pragma unroll
            for (int mi = 0; mi < 4; mi++) {
                uint32_t ah[4];
                uint32_t off = (uint32_t)((wm + mi * 16 + aRow) * LDP + kk * 16 + aCol) * 2;
                ldm_x4(ah[0], ah[1], ah[2], ah[3], db + off);
                #pragma unroll
                for (int nj = 0; nj < 4; nj++)
                    mma_f16(acc[mi][nj], ah, bh[nj]);
            }
        }
        __syncthreads();
        if (kc + 2 < 24) issue(kc + 2, kc & 1);
        CP_COMMIT();
    }

    // ---- epilogue ----
    const int tq = n0 / Cv;
    #pragma unroll
    for (int mi = 0; mi < 4; mi++) {
        #pragma unroll
        for (int nj = 0; nj < 4; nj++) {
            int r = m0 + wm + mi * 16 + (lane >> 2);
            int c = n0 + wn + nj * 8 + 2 * (lane & 3);
            #pragma unroll
            for (int half = 0; half < 2; half++) {
                int rr = r + half * 8;
                float v0 = acc[mi][nj][half * 2 + 0];
                float v1 = acc[mi][nj][half * 2 + 1];
                float2 bi = *(const float2*)(bias + c);
                if (EPI == 0) {
                    int b = rr >> 10;
                    int n = rr & 1023;
                    float2 sg2 = *(const float2*)(g_sig + b * C3 + c);
                    float ox = (v0 + bi.x) * sg2.x;
                    float oy = (v1 + bi.y) * sg2.y;
                    int rem = c - tq * Cv;
                    int h = rem >> 6;
                    int e = rem & 63;
                    size_t idx = ((size_t)(b * Hv + h) * Nv + n) * HD + e;
                    __half* dst = (tq == 0) ? g_qh : (tq == 1) ? g_kh : g_vh;
                    *(uint32_t*)(dst + idx) = pack2h(ox, oy);
                } else {
                    float2 o;
                    o.x = v0 + bi.x;
                    o.y = v1 + bi.y;
                    *(float2*)(out + (size_t)rr * Cv + c) = o;
                }
            }
        }
    }
}

// ======================= fp16 HMMA flash attention: 1-MMA QK^T, 1-MMA PV =======================
#define LDV 72
#define VTILEB (64*LDV*2)           // 9216
#define ABUFB (2*VTILEB)            // KH, VH = 18432
#define ASM_BYTES (2*ABUFB)         // 36864

__global__ __launch_bounds__(256, 2) void attn_mma() {
    extern __shared__ __align__(16) char sm[];
    const uint32_t sb = smem_u32(sm);

    const int tid = threadIdx.x;
    const int wid = tid >> 5;
    const int lane = tid & 31;
    const int bh = blockIdx.y;
    const size_t head_base = (size_t)bh * Nv * HD;
    const int q0 = blockIdx.x * 128 + wid * 16;

    const int grp = lane >> 3, lr = lane & 7;
    const int bRow = (grp >> 1) * 8 + lr;
    const int bCol = (grp & 1) * 8;
    const int vRow = lane & 15;
    const int vCol = (lane >> 4) * 8;

    const int srow = tid >> 3;
    const int sg = tid & 7;

    // ---- Q fragments (fp16) direct from gmem ----
    const int qrow0 = q0 + (lane >> 2);
    const int kcol = (lane & 3) * 2;
    uint32_t qh[4][4];
    {
        const size_t base0 = head_base + (size_t)qrow0 * HD;
        const size_t base1 = base0 + 8 * HD;
        #pragma unroll
        for (int s = 0; s < 4; s++) {
            qh[s][0] = *(const uint32_t*)(g_qh + base0 + s * 16 + kcol);
            qh[s][1] = *(const uint32_t*)(g_qh + base1 + s * 16 + kcol);
            qh[s][2] = *(const uint32_t*)(g_qh + base0 + s * 16 + 8 + kcol);
            qh[s][3] = *(const uint32_t*)(g_qh + base1 + s * 16 + 8 + kcol);
        }
    }

    auto issue = [&](int kt, int bsel) {
        const __half* s0 = g_kh + head_base + (size_t)kt * 64 * HD;
        const __half* s1 = g_vh + head_base + (size_t)kt * 64 * HD;
        const uint32_t db = sb + bsel * ABUFB;
        #pragma unroll
        for (int j = 0; j < 2; j++) {
            int row = srow + j * 32;
            uint32_t doff = (uint32_t)(row * LDV + sg * 8) * 2;
            size_t goff = (size_t)row * HD + sg * 8;
            cp16(db + 0 * VTILEB + doff, s0 + goff);
            cp16(db + 1 * VTILEB + doff, s1 + goff);
        }
    };

    float oacc[8][4] = {};
    float l0 = 0.f, l1 = 0.f;

    issue(0, 0); CP_COMMIT();
    issue(1, 1); CP_COMMIT();

    for (int kt = 0; kt < 16; kt++) {
        CP_WAIT1();
        __syncthreads();
        const uint32_t db = sb + (kt & 1) * ABUFB;
        const uint32_t khb = db;
        const uint32_t vhb = db + VTILEB;

        // ---- S = Q.K^T, exp, pack P ----
        uint32_t pa[4][4];
        #pragma unroll
        for (int np = 0; np < 4; np++) {
            float sc0[4] = {}, sc1[4] = {};
            #pragma unroll
            for (int s = 0; s < 4; s++) {
                uint32_t off = (uint32_t)((np * 16 + bRow) * LDV + s * 16 + bCol) * 2;
                uint32_t h0, h1, h2, h3;
                ldm_x4(h0, h1, h2, h3, khb + off);
                uint32_t bh0[2] = {h0, h1}, bh1[2] = {h2, h3};
                mma_f16(sc0, qh[s], bh0);
                mma_f16(sc1, qh[s], bh1);
            }
            float p00 = __expf(sc0[0] * 0.125f), p01 = __expf(sc0[1] * 0.125f);
            float p02 = __expf(sc0[2] * 0.125f), p03 = __expf(sc0[3] * 0.125f);
            float p10 = __expf(sc1[0] * 0.125f), p11 = __expf(sc1[1] * 0.125f);
            float p12 = __expf(sc1[2] * 0.125f), p13 = __expf(sc1[3] * 0.125f);
            l0 += (p00 + p01) + (p10 + p11);
            l1 += (p02 + p03) + (p12 + p13);
            pa[np][0] = pack2h(p00, p01);
            pa[np][1] = pack2h(p02, p03);
            pa[np][2] = pack2h(p10, p11);
            pa[np][3] = pack2h(p12, p13);
        }

        // ---- O += P.V ----
        #pragma unroll
        for (int jn = 0; jn < 4; jn++) {
            #pragma unroll
            for (int s = 0; s < 4; s++) {
                uint32_t off = (uint32_t)((s * 16 + vRow) * LDV + jn * 16 + vCol) * 2;
                uint32_t h0, h1, h2, h3;
                ldm_x4_t(h0, h1, h2, h3, vhb + off);
                uint32_t bvh0[2] = {h0, h1}, bvh1[2] = {h2, h3};
                mma_f16(oacc[jn * 2],     pa[s], bvh0);
                mma_f16(oacc[jn * 2 + 1], pa[s], bvh1);
            }
        }
        __syncthreads();
        if (kt + 2 < 16) issue(kt + 2, kt & 1);
        CP_COMMIT();
    }

    // ---- normalize + store o (fp16) ----
    l0 += __shfl_xor_sync(0xFFFFFFFFu, l0, 1);
    l0 += __shfl_xor_sync(0xFFFFFFFFu, l0, 2);
    l1 += __shfl_xor_sync(0xFFFFFFFFu, l1, 1);
    l1 += __shfl_xor_sync(0xFFFFFFFFu, l1, 2);
    const float inv0 = 1.0f / l0;
    const float inv1 = 1.0f / l1;

    const int b = bh / Hv;
    const int h = bh - b * Hv;
    const int qg0 = blockIdx.x * 128 + wid * 16 + (lane >> 2);
    const size_t o0 = ((size_t)(b * Nv + qg0)) * Cv + h * HD + kcol;
    const size_t o1 = o0 + 8 * (size_t)Cv;
    #pragma unroll
    for (int j = 0; j < 8; j++) {
        *(uint32_t*)(g_oh + o0 + j * 8) = pack2h(oacc[j][0] * inv0, oacc[j][1] * inv0);
        *(uint32_t*)(g_oh + o1 + j * 8) = pack2h(oacc[j][2] * inv1, oacc[j][3] * inv1);
    }
}

// ======================= launch =======================
extern "C" void kernel_launch(void* const* d_in, const int* in_sizes, int n_in,
                              void* d_out, int out_size) {
    const float* x      = (const float*)d_in[0];
    const int*   label  = (const int*)d_in[1];
    const float* alpha  = (const float*)d_in[2];
    const float* qkv_w  = (const float*)d_in[3];
    const float* qkv_b  = (const float*)d_in[4];
    const float* proj_w = (const float*)d_in[5];
    const float* proj_b = (const float*)d_in[6];
    float* out = (float*)d_out;

    cudaFuncSetAttribute(mma_gemm<0>, cudaFuncAttributeMaxDynamicSharedMemorySize, SM_BYTES);
    cudaFuncSetAttribute(mma_gemm<1>, cudaFuncAttributeMaxDynamicSharedMemorySize, SM_BYTES);
    cudaFuncSetAttribute(attn_mma, cudaFuncAttributeMaxDynamicSharedMemorySize, ASM_BYTES);

    gate_kernel<<<(Bv * C3 + 255) / 256, 256>>>(alpha, label);

    cvt_kernel<0><<<(MT * Cv / 8 + 255) / 256, 256>>>(x, MT * Cv / 8);
    cvt_kernel<1><<<(C3 * Cv / 8 + 255) / 256, 256>>>(qkv_w, C3 * Cv / 8);
    cvt_kernel<2><<<(Cv * Cv / 8 + 255) / 256, 256>>>(proj_w, Cv * Cv / 8);

    mma_gemm<0><<<dim3(C3 / 128, MT / 128), 256, SM_BYTES>>>(qkv_b, nullptr);
    attn_mma<<<dim3(Nv / 128, Bv * Hv), 256, ASM_BYTES>>>();
    mma_gemm<1><<<dim3(Cv / 128, MT / 128), 256, SM_BYTES>>>(proj_b, out);
}